// round 8
// baseline (speedup 1.0000x reference)
#include <cuda_runtime.h>
#include <math.h>

// Problem constants
constexpr int NB  = 4;
constexpr int NC  = 64;
constexpr int NHW = 4096;     // 64*64
constexpr int NKD = 576;      // C*9

// GEMM tiling
constexpr int TM  = 128;
constexpr int TN  = 128;
constexpr int KB  = 16;
constexpr int NKC = NKD / KB; // 36

// Scratch (static __device__: no allocations allowed)
__device__ float g_z[NB * NKD * NHW];     // normalized unfold, [b][d=c*9+j][n]  (~38 MB)
__device__ float g_xt[NB * NHW * NC];     // x transposed to [b][h][w][c]        (4 MB)
__device__ float g_norm[NB * NC * 9];     // per-(b,c,j) L2 norms
__device__ int   g_top[NB * NHW * 3];     // top-3 indices per (b,n)

// ---------------------------------------------------------------------------
// Kernel 1: shifted norms via border decomposition.
// norm^2(kh,kw) = S - (excluded border row/col sums) + (corner add-back)
// ---------------------------------------------------------------------------
__global__ void norms_kernel(const float* __restrict__ x) {
    const int bc = blockIdx.x;                 // 0 .. NB*NC-1
    const float* xp = x + (size_t)bc * NHW;

    float s = 0.f, r0 = 0.f, r63 = 0.f, cl = 0.f, cr = 0.f;
    for (int idx = threadIdx.x; idx < NHW; idx += blockDim.x) {
        float v = xp[idx]; v *= v;
        const int h = idx >> 6, w = idx & 63;
        s += v;
        if (h == 0)  r0  += v;
        if (h == 63) r63 += v;
        if (w == 0)  cl  += v;
        if (w == 63) cr  += v;
    }
    __shared__ float red[5][256];
    red[0][threadIdx.x] = s;  red[1][threadIdx.x] = r0; red[2][threadIdx.x] = r63;
    red[3][threadIdx.x] = cl; red[4][threadIdx.x] = cr;
    __syncthreads();
    for (int o = 128; o > 0; o >>= 1) {
        if (threadIdx.x < o)
            for (int q = 0; q < 5; ++q) red[q][threadIdx.x] += red[q][threadIdx.x + o];
        __syncthreads();
    }
    if (threadIdx.x == 0) {
        const float S = red[0][0], R0 = red[1][0], R63 = red[2][0];
        const float CL = red[3][0], CR = red[4][0];
        float x00 = xp[0],        x0e = xp[63];
        float xe0 = xp[63 * 64],  xee = xp[63 * 64 + 63];
        x00 *= x00; x0e *= x0e; xe0 *= xe0; xee *= xee;
        #pragma unroll
        for (int kh = 0; kh < 3; ++kh)
            #pragma unroll
            for (int kw = 0; kw < 3; ++kw) {
                float n2 = S;
                if (kh == 0) n2 -= R63;   // source row 63 excluded
                if (kh == 2) n2 -= R0;    // source row 0 excluded
                if (kw == 0) n2 -= CR;    // source col 63 excluded
                if (kw == 2) n2 -= CL;    // source col 0 excluded
                if (kh == 0 && kw == 0) n2 += xee;
                if (kh == 0 && kw == 2) n2 += xe0;
                if (kh == 2 && kw == 0) n2 += x0e;
                if (kh == 2 && kw == 2) n2 += x00;
                float nrm = sqrtf(fmaxf(n2, 0.f));
                nrm = fmaxf(nrm, 1e-12f);
                g_norm[bc * 9 + kh * 3 + kw] = nrm;
            }
    }
}

// ---------------------------------------------------------------------------
// Kernel 2a: build normalized unfold z[b][d][n], d = c*9 + (kh*3+kw)
// ---------------------------------------------------------------------------
__global__ void buildz_kernel(const float* __restrict__ x) {
    const int idx = blockIdx.x * blockDim.x + threadIdx.x;
    if (idx >= NB * NKD * NHW) return;
    const int n = idx & (NHW - 1);
    const int d = (idx >> 12) % NKD;
    const int b = idx / (NKD * NHW);
    const int c = d / 9, jj = d % 9;
    const int h = (n >> 6) + jj / 3 - 1;
    const int w = (n & 63) + jj % 3 - 1;
    float v = 0.f;
    if ((unsigned)h < 64u && (unsigned)w < 64u)
        v = __fdiv_rn(x[(((size_t)b * NC + c) * 64 + h) * 64 + w],
                      g_norm[(b * NC + c) * 9 + jj]);
    g_z[idx] = v;
}

// ---------------------------------------------------------------------------
// Kernel 2b: transpose x -> [b][h][w][c] for coalesced channel gathers
// ---------------------------------------------------------------------------
__global__ void transpose_kernel(const float* __restrict__ x) {
    const int idx = blockIdx.x * blockDim.x + threadIdx.x;
    if (idx >= NB * NC * NHW) return;
    const int w = idx & 63;
    const int h = (idx >> 6) & 63;
    const int c = (idx >> 12) & 63;
    const int b = idx >> 18;
    g_xt[(((size_t)b * 64 + h) * 64 + w) * 64 + c] = x[idx];
}

// ---------------------------------------------------------------------------
// Kernel 3: R = Z^T Z (per batch) with fused streaming top-3 per row.
// 128x128 tile, 8x8 per-thread microtile, K-chunks of 16, smem double-buffered
// via register prefetch. R (256MB) is never materialized.
// ---------------------------------------------------------------------------
__global__ __launch_bounds__(256, 1) void gemm_top3_kernel() {
    __shared__ union SMem {
        struct { float A[2][KB][TM]; float Bt[2][KB][TN]; } t;   // 32 KB
        struct { float mv[TM][48];   int   mi[TM][48];    } mg;  // 48 KB
    } sm;

    const int b  = blockIdx.y;
    const int n0 = blockIdx.x * TM;
    const float* __restrict__ Z = g_z + (size_t)b * NKD * NHW;

    const int tid = threadIdx.x;
    const int tx = tid & 15;
    const int ty = tid >> 4;

    const int lr0 = tid >> 5;            // load row 0..7 (and +8)
    const int lc  = (tid & 31) << 2;     // load col in floats (0..124)

    float tv[8][3];
    int   ti[8][3];
    #pragma unroll
    for (int i = 0; i < 8; ++i)
        #pragma unroll
        for (int s = 0; s < 3; ++s) { tv[i][s] = -1e30f; ti[i][s] = 0x7fffffff; }

    for (int mt = 0; mt < NHW / TN; ++mt) {
        const int m0 = mt * TN;
        float acc[8][8];
        #pragma unroll
        for (int i = 0; i < 8; ++i)
            #pragma unroll
            for (int j = 0; j < 8; ++j) acc[i][j] = 0.f;

        {   // chunk 0 -> buffer 0
            const float* a0 = Z + (size_t)lr0 * NHW + n0 + lc;
            const float* b0 = Z + (size_t)lr0 * NHW + m0 + lc;
            *(float4*)&sm.t.A [0][lr0    ][lc] = *(const float4*)(a0);
            *(float4*)&sm.t.A [0][lr0 + 8][lc] = *(const float4*)(a0 + 8 * NHW);
            *(float4*)&sm.t.Bt[0][lr0    ][lc] = *(const float4*)(b0);
            *(float4*)&sm.t.Bt[0][lr0 + 8][lc] = *(const float4*)(b0 + 8 * NHW);
        }
        __syncthreads();

        for (int kc = 0; kc < NKC; ++kc) {
            const int buf = kc & 1;
            float4 pa0, pa1, pb0, pb1;
            const bool np = (kc + 1 < NKC);
            if (np) {
                const int k0 = (kc + 1) * KB;
                const float* a0 = Z + (size_t)(k0 + lr0) * NHW + n0 + lc;
                const float* b0 = Z + (size_t)(k0 + lr0) * NHW + m0 + lc;
                pa0 = *(const float4*)(a0);
                pa1 = *(const float4*)(a0 + 8 * NHW);
                pb0 = *(const float4*)(b0);
                pb1 = *(const float4*)(b0 + 8 * NHW);
            }
            #pragma unroll
            for (int k = 0; k < KB; ++k) {
                const float4 av0 = *(const float4*)&sm.t.A [buf][k][ty * 8];
                const float4 av1 = *(const float4*)&sm.t.A [buf][k][ty * 8 + 4];
                const float4 bv0 = *(const float4*)&sm.t.Bt[buf][k][tx * 8];
                const float4 bv1 = *(const float4*)&sm.t.Bt[buf][k][tx * 8 + 4];
                const float a[8]  = {av0.x, av0.y, av0.z, av0.w, av1.x, av1.y, av1.z, av1.w};
                const float bb[8] = {bv0.x, bv0.y, bv0.z, bv0.w, bv1.x, bv1.y, bv1.z, bv1.w};
                #pragma unroll
                for (int i = 0; i < 8; ++i)
                    #pragma unroll
                    for (int j = 0; j < 8; ++j)
                        acc[i][j] = fmaf(a[i], bb[j], acc[i][j]);
            }
            if (np) {
                const int nb = buf ^ 1;
                *(float4*)&sm.t.A [nb][lr0    ][lc] = pa0;
                *(float4*)&sm.t.A [nb][lr0 + 8][lc] = pa1;
                *(float4*)&sm.t.Bt[nb][lr0    ][lc] = pb0;
                *(float4*)&sm.t.Bt[nb][lr0 + 8][lc] = pb1;
            }
            __syncthreads();
        }

        // Streaming top-3 update (ascending m; strict '>' keeps lowest index)
        #pragma unroll
        for (int i = 0; i < 8; ++i) {
            #pragma unroll
            for (int j = 0; j < 8; ++j) {
                const float v = acc[i][j];
                const int m = m0 + tx * 8 + j;
                if (v > tv[i][2]) {
                    if (v > tv[i][1]) {
                        if (v > tv[i][0]) {
                            tv[i][2] = tv[i][1]; ti[i][2] = ti[i][1];
                            tv[i][1] = tv[i][0]; ti[i][1] = ti[i][0];
                            tv[i][0] = v;        ti[i][0] = m;
                        } else {
                            tv[i][2] = tv[i][1]; ti[i][2] = ti[i][1];
                            tv[i][1] = v;        ti[i][1] = m;
                        }
                    } else {
                        tv[i][2] = v; ti[i][2] = m;
                    }
                }
            }
        }
    }

    __syncthreads();  // all tile reads done before union reuse

    #pragma unroll
    for (int i = 0; i < 8; ++i) {
        const int r = ty * 8 + i;
        #pragma unroll
        for (int s = 0; s < 3; ++s) {
            sm.mg.mv[r][tx * 3 + s] = tv[i][s];
            sm.mg.mi[r][tx * 3 + s] = ti[i][s];
        }
    }
    __syncthreads();

    if (tid < TM) {
        float b0v = -1e30f, b1v = -1e30f, b2v = -1e30f;
        int   j0 = 0x7fffffff, j1 = 0x7fffffff, j2 = 0x7fffffff;
        for (int e = 0; e < 48; ++e) {
            const float v = sm.mg.mv[tid][e];
            const int   m = sm.mg.mi[tid][e];
            if (v > b2v || (v == b2v && m < j2)) {
                if (v > b1v || (v == b1v && m < j1)) {
                    if (v > b0v || (v == b0v && m < j0)) {
                        b2v = b1v; j2 = j1;
                        b1v = b0v; j1 = j0;
                        b0v = v;   j0 = m;
                    } else {
                        b2v = b1v; j2 = j1;
                        b1v = v;   j1 = m;
                    }
                } else {
                    b2v = v; j2 = m;
                }
            }
        }
        const int base = (b * NHW + n0 + tid) * 3;
        g_top[base] = j0; g_top[base + 1] = j1; g_top[base + 2] = j2;
    }
}

// ---------------------------------------------------------------------------
// Kernel 4: gather K (with the reference's scrambled reshape!), scores,
// softmax, weighted sum. One warp per (b, n); lane handles channels c, c+32.
//
// Reference reshape: K[b,n,k*9+r,c] = xu[b, r*64+c, m_k], where xu feature
// index d = c'*9 + j' (channel-major unfold). So d = r*64+c -> c'=d/9, j'=d%9.
// ---------------------------------------------------------------------------
__device__ __forceinline__ float gatherK(const float* __restrict__ xt_b, int b,
                                         int mh, int mw, int r, int c) {
    const int d  = r * 64 + c;
    const int cc = d / 9;
    const int jj = d - cc * 9;
    const int hh = mh + jj / 3 - 1;
    const int ww = mw + jj % 3 - 1;
    float v = 0.f;
    if ((unsigned)hh < 64u && (unsigned)ww < 64u)
        v = __fdiv_rn(xt_b[(hh * 64 + ww) * 64 + cc],
                      g_norm[(b * NC + cc) * 9 + jj]);
    return v;
}

__global__ void attn_kernel(float* __restrict__ out) {
    const int gw = (blockIdx.x * blockDim.x + threadIdx.x) >> 5;
    const int lane = threadIdx.x & 31;
    if (gw >= NB * NHW) return;
    const int b = gw >> 12;
    const int n = gw & (NHW - 1);
    const int h = n >> 6, w = n & 63;
    const int c0 = lane, c1 = lane + 32;

    const float* __restrict__ xt_b = g_xt + (size_t)b * NHW * NC;
    const float q0 = xt_b[(h * 64 + w) * 64 + c0];
    const float q1 = xt_b[(h * 64 + w) * 64 + c1];

    int mi[3];
    mi[0] = g_top[gw * 3];
    mi[1] = g_top[gw * 3 + 1];
    mi[2] = g_top[gw * 3 + 2];

    float kv0[27], kv1[27];
    #pragma unroll
    for (int k = 0; k < 3; ++k) {
        const int mh = mi[k] >> 6, mw = mi[k] & 63;
        #pragma unroll
        for (int r = 0; r < 9; ++r) {
            kv0[k * 9 + r] = gatherK(xt_b, b, mh, mw, r, c0);
            kv1[k * 9 + r] = gatherK(xt_b, b, mh, mw, r, c1);
        }
    }

    float s[27];
    #pragma unroll
    for (int e = 0; e < 27; ++e) {
        float t = q0 * kv0[e] + q1 * kv1[e];
        #pragma unroll
        for (int o = 16; o > 0; o >>= 1) t += __shfl_xor_sync(0xffffffffu, t, o);
        s[e] = t * 0.125f;   // / sqrt(64)
    }

    float mx = s[0];
    #pragma unroll
    for (int e = 1; e < 27; ++e) mx = fmaxf(mx, s[e]);
    float sum = 0.f;
    #pragma unroll
    for (int e = 0; e < 27; ++e) { s[e] = expf(s[e] - mx); sum += s[e]; }

    float o0 = 0.f, o1 = 0.f;
    #pragma unroll
    for (int e = 0; e < 27; ++e) {
        const float we = __fdiv_rn(s[e], sum);
        o0 += we * kv0[e];
        o1 += we * kv1[e];
    }
    out[(size_t)gw * 64 + c0] = o0;
    out[(size_t)gw * 64 + c1] = o1;
}

// ---------------------------------------------------------------------------
extern "C" void kernel_launch(void* const* d_in, const int* in_sizes, int n_in,
                              void* d_out, int out_size) {
    const float* x = (const float*)d_in[0];
    float* out = (float*)d_out;

    norms_kernel<<<NB * NC, 256>>>(x);
    buildz_kernel<<<(NB * NKD * NHW + 255) / 256, 256>>>(x);
    transpose_kernel<<<(NB * NC * NHW + 255) / 256, 256>>>(x);
    dim3 g3(NHW / TM, NB);
    gemm_top3_kernel<<<g3, 256>>>();
    attn_kernel<<<(NB * NHW * 32 + 255) / 256, 256>>>(out);
}

// round 10
// speedup vs baseline: 2.1049x; 2.1049x over previous
#include <cuda_runtime.h>
#include <cuda_bf16.h>
#include <math.h>
#include <stdint.h>

// Problem constants
constexpr int NB  = 4;
constexpr int NC  = 64;
constexpr int NHW = 4096;     // 64*64
constexpr int NKD = 576;      // C*9

// Split-K bf16 GEMM config
constexpr int KP     = 1152;          // stored K' = [hi(576) | lo(576)]
constexpr int ROWB   = KP * 2;        // 2304 bytes per n-row
constexpr int TTM    = 128;           // rows (n) per CTA
constexpr int TTN    = 256;           // cols (m) per m-step
constexpr int NMT    = NHW / TTN;     // 16 m-steps
constexpr int NCHUNK = 27;            // 27 x 64 = effective K 1728 (hihi+lohi+hilo)
constexpr int NG     = NMT * NCHUNK;  // 432 chunks total

// Scratch (static __device__: no allocations allowed)
__device__ __nv_bfloat16 g_za[(size_t)NB * NHW * KP];   // [b][n][hi|lo]  ~37.7MB
__device__ float g_xt[NB * NHW * NC];                   // x -> [b][h][w][c]
__device__ float g_norm[NB * NC * 9];                   // per-(b,c,j) L2 norms
__device__ int   g_top[NB * NHW * 3];                   // top-3 indices per (b,n)

// ---------------------------------------------------------------------------
// PTX helpers (all sm_80-era: safe for plain sm_103 ptxas target)
// ---------------------------------------------------------------------------
__device__ __forceinline__ uint32_t s2u(const void* p) {
    uint32_t a;
    asm("{ .reg .u64 t; cvta.to.shared.u64 t, %1; cvt.u32.u64 %0, t; }"
        : "=r"(a) : "l"(p));
    return a;
}
__device__ __forceinline__ void cp16(uint32_t s, const void* g) {
    asm volatile("cp.async.cg.shared.global [%0], [%1], 16;"
                 :: "r"(s), "l"(g) : "memory");
}
#define CP_COMMIT()  asm volatile("cp.async.commit_group;" ::: "memory")
#define CP_WAIT1()   asm volatile("cp.async.wait_group 1;" ::: "memory")
#define CP_WAIT0()   asm volatile("cp.async.wait_group 0;" ::: "memory")

#define LDSM4(r0, r1, r2, r3, a) \
    asm volatile("ldmatrix.sync.aligned.m8n8.x4.shared.b16 {%0,%1,%2,%3}, [%4];" \
                 : "=r"(r0), "=r"(r1), "=r"(r2), "=r"(r3) : "r"(a))

__device__ __forceinline__ void mma16816(float* c, uint32_t a0, uint32_t a1,
                                         uint32_t a2, uint32_t a3,
                                         uint32_t b0, uint32_t b1) {
    asm volatile(
        "mma.sync.aligned.m16n8k16.row.col.f32.bf16.bf16.f32 "
        "{%0,%1,%2,%3}, {%4,%5,%6,%7}, {%8,%9}, {%0,%1,%2,%3};"
        : "+f"(c[0]), "+f"(c[1]), "+f"(c[2]), "+f"(c[3])
        : "r"(a0), "r"(a1), "r"(a2), "r"(a3), "r"(b0), "r"(b1));
}

__device__ __forceinline__ void top3upd(float tv[3], int ti[3], float v, int m) {
    if (v > tv[2]) {
        if (v > tv[1]) {
            if (v > tv[0]) {
                tv[2] = tv[1]; ti[2] = ti[1];
                tv[1] = tv[0]; ti[1] = ti[0];
                tv[0] = v;     ti[0] = m;
            } else {
                tv[2] = tv[1]; ti[2] = ti[1];
                tv[1] = v;     ti[1] = m;
            }
        } else {
            tv[2] = v; ti[2] = m;
        }
    }
}

// Dynamic smem layout for the GEMM kernel
constexpr int OFF_A = 0;        // bufA[2] : 2 x 16 KB (128 rows x 128 B)
constexpr int OFF_B = 32768;    // bufB[2] : 2 x 32 KB (256 rows x 128 B)
constexpr int SMEMB = 98304;    // 96 KB

// ---------------------------------------------------------------------------
// Kernel 1: shifted norms via border decomposition.
// ---------------------------------------------------------------------------
__global__ void norms_kernel(const float* __restrict__ x) {
    const int bc = blockIdx.x;
    const float* xp = x + (size_t)bc * NHW;

    float s = 0.f, r0 = 0.f, r63 = 0.f, cl = 0.f, cr = 0.f;
    for (int idx = threadIdx.x; idx < NHW; idx += blockDim.x) {
        float v = xp[idx]; v *= v;
        const int h = idx >> 6, w = idx & 63;
        s += v;
        if (h == 0)  r0  += v;
        if (h == 63) r63 += v;
        if (w == 0)  cl  += v;
        if (w == 63) cr  += v;
    }
    __shared__ float red[5][256];
    red[0][threadIdx.x] = s;  red[1][threadIdx.x] = r0; red[2][threadIdx.x] = r63;
    red[3][threadIdx.x] = cl; red[4][threadIdx.x] = cr;
    __syncthreads();
    for (int o = 128; o > 0; o >>= 1) {
        if (threadIdx.x < o)
            for (int q = 0; q < 5; ++q) red[q][threadIdx.x] += red[q][threadIdx.x + o];
        __syncthreads();
    }
    if (threadIdx.x == 0) {
        const float S = red[0][0], R0 = red[1][0], R63 = red[2][0];
        const float CL = red[3][0], CR = red[4][0];
        float x00 = xp[0],        x0e = xp[63];
        float xe0 = xp[63 * 64],  xee = xp[63 * 64 + 63];
        x00 *= x00; x0e *= x0e; xe0 *= xe0; xee *= xee;
        #pragma unroll
        for (int kh = 0; kh < 3; ++kh)
            #pragma unroll
            for (int kw = 0; kw < 3; ++kw) {
                float n2 = S;
                if (kh == 0) n2 -= R63;
                if (kh == 2) n2 -= R0;
                if (kw == 0) n2 -= CR;
                if (kw == 2) n2 -= CL;
                if (kh == 0 && kw == 0) n2 += xee;
                if (kh == 0 && kw == 2) n2 += xe0;
                if (kh == 2 && kw == 0) n2 += x0e;
                if (kh == 2 && kw == 2) n2 += x00;
                float nrm = sqrtf(fmaxf(n2, 0.f));
                nrm = fmaxf(nrm, 1e-12f);
                g_norm[bc * 9 + kh * 3 + kw] = nrm;
            }
    }
}

// ---------------------------------------------------------------------------
// Kernel 2a: build split-bf16 normalized unfold, transposed to [b][n][hi|lo].
// ---------------------------------------------------------------------------
__global__ void splitz_kernel(const float* __restrict__ x) {
    __shared__ float tl[32][33];
    const int b = blockIdx.z, d0 = blockIdx.y * 32, n0 = blockIdx.x * 32;
    const int tx = threadIdx.x, ty = threadIdx.y;   // 32x8
    #pragma unroll
    for (int i = 0; i < 4; ++i) {
        const int d = d0 + ty + i * 8, n = n0 + tx;
        const int c = d / 9, jj = d - c * 9;
        const int h = (n >> 6) + jj / 3 - 1, w = (n & 63) + jj % 3 - 1;
        float v = 0.f;
        if ((unsigned)h < 64u && (unsigned)w < 64u)
            v = __fdiv_rn(x[(((size_t)b * NC + c) * 64 + h) * 64 + w],
                          g_norm[(b * NC + c) * 9 + jj]);
        tl[ty + i * 8][tx] = v;
    }
    __syncthreads();
    #pragma unroll
    for (int i = 0; i < 4; ++i) {
        const int n = n0 + ty + i * 8, d = d0 + tx;
        const float z = tl[tx][ty + i * 8];
        const __nv_bfloat16 h = __float2bfloat16(z);
        const __nv_bfloat16 l = __float2bfloat16(z - __bfloat162float(h));
        __nv_bfloat16* row = g_za + ((size_t)b * NHW + n) * KP;
        row[d] = h;
        row[576 + d] = l;
    }
}

// ---------------------------------------------------------------------------
// Kernel 2b: transpose x -> [b][h][w][c]
// ---------------------------------------------------------------------------
__global__ void transpose_kernel(const float* __restrict__ x) {
    const int idx = blockIdx.x * blockDim.x + threadIdx.x;
    if (idx >= NB * NC * NHW) return;
    const int w = idx & 63;
    const int h = (idx >> 6) & 63;
    const int c = (idx >> 12) & 63;
    const int b = idx >> 18;
    g_xt[(((size_t)b * 64 + h) * 64 + w) * 64 + c] = x[idx];
}

// ---------------------------------------------------------------------------
// Kernel 3: HMMA bf16 split GEMM (R = Z^T Z) with fused streaming top-3.
// 512 threads, 16 warps as 8(rows)x2(cols), warp tile 16x128,
// mma.m16n8k16, cp.async double-buffered K-chunks of 64.
// ---------------------------------------------------------------------------
__device__ __forceinline__ void issue_chunk(const char* zb, int n0, int g,
                                            uint32_t smb, int tid) {
    const int mt = g / NCHUNK, kc = g - mt * NCHUNK;
    const int m0 = mt * TTN;
    const int seg = kc / 9, sub = kc - seg * 9;
    const int aoff2 = (((seg == 1) ? 576 : 0) + sub * 64) * 2;  // bytes
    const int boff2 = (((seg == 2) ? 576 : 0) + sub * 64) * 2;
    const uint32_t sA = smb + OFF_A + (g & 1) * 16384;
    const uint32_t sB = smb + OFF_B + (g & 1) * 32768;
    #pragma unroll
    for (int i = 0; i < 2; ++i) {           // A: 128 rows x 128 B
        const int s = tid + i * 512, row = s >> 3, cb = (s & 7) * 16;
        cp16(sA + row * 128 + (cb ^ ((row & 7) << 4)),
             zb + (size_t)(n0 + row) * ROWB + aoff2 + cb);
    }
    #pragma unroll
    for (int i = 0; i < 4; ++i) {           // B: 256 rows x 128 B
        const int s = tid + i * 512, row = s >> 3, cb = (s & 7) * 16;
        cp16(sB + row * 128 + (cb ^ ((row & 7) << 4)),
             zb + (size_t)(m0 + row) * ROWB + boff2 + cb);
    }
    CP_COMMIT();
}

__global__ __launch_bounds__(512, 1) void gemm_top3_mma() {
    extern __shared__ char sm[];
    const int tid = threadIdx.x, wid = tid >> 5, lane = tid & 31;
    const int b = blockIdx.y, n0 = blockIdx.x * TTM;
    const char* zb = (const char*)g_za + (size_t)b * NHW * ROWB;
    const uint32_t smb = s2u(sm);

    const int wr = wid >> 1, wc = wid & 1;    // warp tile: rows wr*16, cols wc*128
    const int quad = lane >> 3, qr = lane & 7;

    // ldmatrix per-thread row/col components
    const int arow  = wr * 16 + (quad & 1) * 8 + qr;     // A: a0/a1 k-lo, a2/a3 k-hi
    const int akb   = (quad >> 1) * 16;
    const int brow0 = wc * 128 + (quad >> 1) * 8 + qr;   // B: frag pair rows
    const int bkb   = (quad & 1) * 16;

    float tv0[3] = {-1e30f, -1e30f, -1e30f}, tv1[3] = {-1e30f, -1e30f, -1e30f};
    int   ti0[3] = {0x7fffffff, 0x7fffffff, 0x7fffffff};
    int   ti1[3] = {0x7fffffff, 0x7fffffff, 0x7fffffff};

    issue_chunk(zb, n0, 0, smb, tid);

    int g = 0;
    for (int mt = 0; mt < NMT; ++mt) {
        float acc[16][4];
        #pragma unroll
        for (int nj = 0; nj < 16; ++nj)
            #pragma unroll
            for (int q = 0; q < 4; ++q) acc[nj][q] = 0.f;

        for (int kc = 0; kc < NCHUNK; ++kc, ++g) {
            if (g + 1 < NG) { issue_chunk(zb, n0, g + 1, smb, tid); CP_WAIT1(); }
            else            { CP_WAIT0(); }
            __syncthreads();

            const uint32_t sA = smb + OFF_A + (g & 1) * 16384;
            const uint32_t sB = smb + OFF_B + (g & 1) * 32768;
            #pragma unroll
            for (int ks = 0; ks < 4; ++ks) {
                uint32_t a0, a1, a2, a3;
                {
                    const int kb = ks * 32 + akb;
                    LDSM4(a0, a1, a2, a3,
                          sA + arow * 128 + (kb ^ ((arow & 7) << 4)));
                }
                #pragma unroll
                for (int njp = 0; njp < 8; ++njp) {
                    uint32_t b0, b1, b2, b3;
                    const int brow = brow0 + njp * 16;
                    const int kb = ks * 32 + bkb;
                    LDSM4(b0, b1, b2, b3,
                          sB + brow * 128 + (kb ^ ((brow & 7) << 4)));
                    mma16816(acc[njp * 2],     a0, a1, a2, a3, b0, b1);
                    mma16816(acc[njp * 2 + 1], a0, a1, a2, a3, b2, b3);
                }
            }
            __syncthreads();
        }

        // Streaming top-3 update for this m-step (ascending m; '>' keeps lowest idx)
        const int mbase = mt * TTN + wc * 128 + (lane & 3) * 2;
        #pragma unroll
        for (int nj = 0; nj < 16; ++nj) {
            const int mcol = mbase + nj * 8;
            top3upd(tv0, ti0, acc[nj][0], mcol);
            top3upd(tv0, ti0, acc[nj][1], mcol + 1);
            top3upd(tv1, ti1, acc[nj][2], mcol);
            top3upd(tv1, ti1, acc[nj][3], mcol + 1);
        }
    }

    // Merge 8 candidate sets per row (2 warp-cols x 4 lanes); tie -> lower index
    __syncthreads();
    float* cv = (float*)sm;                 // [128][8][3]  12 KB
    int*   ci = (int*)(sm + 12288);         // [128][8][3]  12 KB
    const int r0   = wr * 16 + (lane >> 2);
    const int slot = wc * 4 + (lane & 3);
    #pragma unroll
    for (int s = 0; s < 3; ++s) {
        cv[r0 * 24 + slot * 3 + s]       = tv0[s];
        ci[r0 * 24 + slot * 3 + s]       = ti0[s];
        cv[(r0 + 8) * 24 + slot * 3 + s] = tv1[s];
        ci[(r0 + 8) * 24 + slot * 3 + s] = ti1[s];
    }
    __syncthreads();
    if (tid < TTM) {
        float b0v = -1e30f, b1v = -1e30f, b2v = -1e30f;
        int   j0 = 0x7fffffff, j1 = 0x7fffffff, j2 = 0x7fffffff;
        #pragma unroll
        for (int e = 0; e < 24; ++e) {
            const float v = cv[tid * 24 + e];
            const int   m = ci[tid * 24 + e];
            if (v > b2v || (v == b2v && m < j2)) {
                if (v > b1v || (v == b1v && m < j1)) {
                    if (v > b0v || (v == b0v && m < j0)) {
                        b2v = b1v; j2 = j1;
                        b1v = b0v; j1 = j0;
                        b0v = v;   j0 = m;
                    } else {
                        b2v = b1v; j2 = j1;
                        b1v = v;   j1 = m;
                    }
                } else {
                    b2v = v; j2 = m;
                }
            }
        }
        const int base = (b * NHW + n0 + tid) * 3;
        g_top[base] = j0; g_top[base + 1] = j1; g_top[base + 2] = j2;
    }
}

// ---------------------------------------------------------------------------
// Kernel 4: gather K (reference's scrambled reshape), scores, softmax, output.
// ---------------------------------------------------------------------------
__device__ __forceinline__ float gatherK(const float* __restrict__ xt_b, int b,
                                         int mh, int mw, int r, int c) {
    const int d  = r * 64 + c;
    const int cc = d / 9;
    const int jj = d - cc * 9;
    const int hh = mh + jj / 3 - 1;
    const int ww = mw + jj % 3 - 1;
    float v = 0.f;
    if ((unsigned)hh < 64u && (unsigned)ww < 64u)
        v = __fdiv_rn(xt_b[(hh * 64 + ww) * 64 + cc],
                      g_norm[(b * NC + cc) * 9 + jj]);
    return v;
}

__global__ void attn_kernel(float* __restrict__ out) {
    const int gw = (blockIdx.x * blockDim.x + threadIdx.x) >> 5;
    const int lane = threadIdx.x & 31;
    if (gw >= NB * NHW) return;
    const int b = gw >> 12;
    const int n = gw & (NHW - 1);
    const int h = n >> 6, w = n & 63;
    const int c0 = lane, c1 = lane + 32;

    const float* __restrict__ xt_b = g_xt + (size_t)b * NHW * NC;
    const float q0 = xt_b[(h * 64 + w) * 64 + c0];
    const float q1 = xt_b[(h * 64 + w) * 64 + c1];

    int mi[3];
    mi[0] = g_top[gw * 3];
    mi[1] = g_top[gw * 3 + 1];
    mi[2] = g_top[gw * 3 + 2];

    float kv0[27], kv1[27];
    #pragma unroll
    for (int k = 0; k < 3; ++k) {
        const int mh = mi[k] >> 6, mw = mi[k] & 63;
        #pragma unroll
        for (int r = 0; r < 9; ++r) {
            kv0[k * 9 + r] = gatherK(xt_b, b, mh, mw, r, c0);
            kv1[k * 9 + r] = gatherK(xt_b, b, mh, mw, r, c1);
        }
    }

    float s[27];
    #pragma unroll
    for (int e = 0; e < 27; ++e) {
        float t = q0 * kv0[e] + q1 * kv1[e];
        #pragma unroll
        for (int o = 16; o > 0; o >>= 1) t += __shfl_xor_sync(0xffffffffu, t, o);
        s[e] = t * 0.125f;   // / sqrt(64)
    }

    float mx = s[0];
    #pragma unroll
    for (int e = 1; e < 27; ++e) mx = fmaxf(mx, s[e]);
    float sum = 0.f;
    #pragma unroll
    for (int e = 0; e < 27; ++e) { s[e] = expf(s[e] - mx); sum += s[e]; }

    float o0 = 0.f, o1 = 0.f;
    #pragma unroll
    for (int e = 0; e < 27; ++e) {
        const float we = __fdiv_rn(s[e], sum);
        o0 += we * kv0[e];
        o1 += we * kv1[e];
    }
    out[(size_t)gw * 64 + c0] = o0;
    out[(size_t)gw * 64 + c1] = o1;
}

// ---------------------------------------------------------------------------
extern "C" void kernel_launch(void* const* d_in, const int* in_sizes, int n_in,
                              void* d_out, int out_size) {
    const float* x = (const float*)d_in[0];
    float* out = (float*)d_out;

    norms_kernel<<<NB * NC, 256>>>(x);
    splitz_kernel<<<dim3(NHW / 32, NKD / 32, NB), dim3(32, 8)>>>(x);
    transpose_kernel<<<(NB * NC * NHW + 255) / 256, 256>>>(x);

    cudaFuncSetAttribute(gemm_top3_mma,
                         cudaFuncAttributeMaxDynamicSharedMemorySize, SMEMB);
    gemm_top3_mma<<<dim3(NHW / TTM, NB), 512, SMEMB>>>();

    attn_kernel<<<(NB * NHW * 32 + 255) / 256, 256>>>(out);
}

// round 11
// speedup vs baseline: 2.1877x; 1.0393x over previous
#include <cuda_runtime.h>
#include <cuda_bf16.h>
#include <math.h>
#include <stdint.h>

// Problem constants
constexpr int NB  = 4;
constexpr int NC  = 64;
constexpr int NHW = 4096;     // 64*64
constexpr int NKD = 576;      // C*9

// Split-K bf16 GEMM config
constexpr int KP     = 1152;          // stored K' = [hi(576) | lo(576)]
constexpr int ROWB   = KP * 2;        // 2304 bytes per n-row
constexpr int TTM    = 128;           // rows (n) per CTA
constexpr int TTN    = 256;           // cols (m) per m-step
constexpr int NMT    = NHW / TTN;     // 16 m-steps
constexpr int NCHUNK = 27;            // 27 x 64 = effective K 1728 (hihi+lohi+hilo)
constexpr int NG     = NMT * NCHUNK;  // 432 chunks total

constexpr int STAGE  = 49152;         // A 16KB + B 32KB per stage
constexpr int SMEMB  = 4 * STAGE;     // 192 KB, 4-stage pipeline

// Scratch (static __device__: no allocations allowed)
__device__ __nv_bfloat16 g_za[(size_t)NB * NHW * KP];   // [b][n][hi|lo]  ~37.7MB
__device__ float g_xt[NB * NHW * NC];                   // x -> [b][h][w][c]
__device__ float g_norm[NB * NC * 9];                   // per-(b,c,j) L2 norms
__device__ int   g_top[NB * NHW * 3];                   // top-3 indices per (b,n)

// ---------------------------------------------------------------------------
// PTX helpers (sm_80-era: safe for plain sm_103 ptxas target)
// ---------------------------------------------------------------------------
__device__ __forceinline__ uint32_t s2u(const void* p) {
    uint32_t a;
    asm("{ .reg .u64 t; cvta.to.shared.u64 t, %1; cvt.u32.u64 %0, t; }"
        : "=r"(a) : "l"(p));
    return a;
}
__device__ __forceinline__ void cp16(uint32_t s, const void* g) {
    asm volatile("cp.async.cg.shared.global [%0], [%1], 16;"
                 :: "r"(s), "l"(g) : "memory");
}
#define CP_COMMIT()  asm volatile("cp.async.commit_group;" ::: "memory")
#define CP_WAIT2()   asm volatile("cp.async.wait_group 2;" ::: "memory")

#define LDSM4(r0, r1, r2, r3, a) \
    asm volatile("ldmatrix.sync.aligned.m8n8.x4.shared.b16 {%0,%1,%2,%3}, [%4];" \
                 : "=r"(r0), "=r"(r1), "=r"(r2), "=r"(r3) : "r"(a))

__device__ __forceinline__ void mma16816(float* c, uint32_t a0, uint32_t a1,
                                         uint32_t a2, uint32_t a3,
                                         uint32_t b0, uint32_t b1) {
    asm volatile(
        "mma.sync.aligned.m16n8k16.row.col.f32.bf16.bf16.f32 "
        "{%0,%1,%2,%3}, {%4,%5,%6,%7}, {%8,%9}, {%0,%1,%2,%3};"
        : "+f"(c[0]), "+f"(c[1]), "+f"(c[2]), "+f"(c[3])
        : "r"(a0), "r"(a1), "r"(a2), "r"(a3), "r"(b0), "r"(b1));
}

__device__ __forceinline__ void top3upd(float tv[3], int ti[3], float v, int m) {
    if (v > tv[2]) {
        if (v > tv[1]) {
            if (v > tv[0]) {
                tv[2] = tv[1]; ti[2] = ti[1];
                tv[1] = tv[0]; ti[1] = ti[0];
                tv[0] = v;     ti[0] = m;
            } else {
                tv[2] = tv[1]; ti[2] = ti[1];
                tv[1] = v;     ti[1] = m;
            }
        } else {
            tv[2] = v; ti[2] = m;
        }
    }
}

// ---------------------------------------------------------------------------
// Kernel 1: shifted norms via border decomposition.
// ---------------------------------------------------------------------------
__global__ void norms_kernel(const float* __restrict__ x) {
    const int bc = blockIdx.x;
    const float* xp = x + (size_t)bc * NHW;

    float s = 0.f, r0 = 0.f, r63 = 0.f, cl = 0.f, cr = 0.f;
    for (int idx = threadIdx.x; idx < NHW; idx += blockDim.x) {
        float v = xp[idx]; v *= v;
        const int h = idx >> 6, w = idx & 63;
        s += v;
        if (h == 0)  r0  += v;
        if (h == 63) r63 += v;
        if (w == 0)  cl  += v;
        if (w == 63) cr  += v;
    }
    __shared__ float red[5][256];
    red[0][threadIdx.x] = s;  red[1][threadIdx.x] = r0; red[2][threadIdx.x] = r63;
    red[3][threadIdx.x] = cl; red[4][threadIdx.x] = cr;
    __syncthreads();
    for (int o = 128; o > 0; o >>= 1) {
        if (threadIdx.x < o)
            for (int q = 0; q < 5; ++q) red[q][threadIdx.x] += red[q][threadIdx.x + o];
        __syncthreads();
    }
    if (threadIdx.x == 0) {
        const float S = red[0][0], R0 = red[1][0], R63 = red[2][0];
        const float CL = red[3][0], CR = red[4][0];
        float x00 = xp[0],        x0e = xp[63];
        float xe0 = xp[63 * 64],  xee = xp[63 * 64 + 63];
        x00 *= x00; x0e *= x0e; xe0 *= xe0; xee *= xee;
        #pragma unroll
        for (int kh = 0; kh < 3; ++kh)
            #pragma unroll
            for (int kw = 0; kw < 3; ++kw) {
                float n2 = S;
                if (kh == 0) n2 -= R63;
                if (kh == 2) n2 -= R0;
                if (kw == 0) n2 -= CR;
                if (kw == 2) n2 -= CL;
                if (kh == 0 && kw == 0) n2 += xee;
                if (kh == 0 && kw == 2) n2 += xe0;
                if (kh == 2 && kw == 0) n2 += x0e;
                if (kh == 2 && kw == 2) n2 += x00;
                float nrm = sqrtf(fmaxf(n2, 0.f));
                nrm = fmaxf(nrm, 1e-12f);
                g_norm[bc * 9 + kh * 3 + kw] = nrm;
            }
    }
}

// ---------------------------------------------------------------------------
// Kernel 2a: build split-bf16 normalized unfold, transposed to [b][n][hi|lo].
// ---------------------------------------------------------------------------
__global__ void splitz_kernel(const float* __restrict__ x) {
    __shared__ float tl[32][33];
    const int b = blockIdx.z, d0 = blockIdx.y * 32, n0 = blockIdx.x * 32;
    const int tx = threadIdx.x, ty = threadIdx.y;   // 32x8
    #pragma unroll
    for (int i = 0; i < 4; ++i) {
        const int d = d0 + ty + i * 8, n = n0 + tx;
        const int c = d / 9, jj = d - c * 9;
        const int h = (n >> 6) + jj / 3 - 1, w = (n & 63) + jj % 3 - 1;
        float v = 0.f;
        if ((unsigned)h < 64u && (unsigned)w < 64u)
            v = __fdiv_rn(x[(((size_t)b * NC + c) * 64 + h) * 64 + w],
                          g_norm[(b * NC + c) * 9 + jj]);
        tl[ty + i * 8][tx] = v;
    }
    __syncthreads();
    #pragma unroll
    for (int i = 0; i < 4; ++i) {
        const int n = n0 + ty + i * 8, d = d0 + tx;
        const float z = tl[tx][ty + i * 8];
        const __nv_bfloat16 h = __float2bfloat16(z);
        const __nv_bfloat16 l = __float2bfloat16(z - __bfloat162float(h));
        __nv_bfloat16* row = g_za + ((size_t)b * NHW + n) * KP;
        row[d] = h;
        row[576 + d] = l;
    }
}

// ---------------------------------------------------------------------------
// Kernel 2b: transpose x -> [b][h][w][c]
// ---------------------------------------------------------------------------
__global__ void transpose_kernel(const float* __restrict__ x) {
    const int idx = blockIdx.x * blockDim.x + threadIdx.x;
    if (idx >= NB * NC * NHW) return;
    const int w = idx & 63;
    const int h = (idx >> 6) & 63;
    const int c = (idx >> 12) & 63;
    const int b = idx >> 18;
    g_xt[(((size_t)b * 64 + h) * 64 + w) * 64 + c] = x[idx];
}

// ---------------------------------------------------------------------------
// Kernel 3: HMMA bf16 split GEMM (R = Z^T Z) with fused streaming top-3.
// 256 threads, 8 warps as 4(rows)x2(cols), warp tile 32x128, mma.m16n8k16,
// 4-stage cp.async pipeline, one __syncthreads per chunk.
// ---------------------------------------------------------------------------
__device__ __forceinline__ void issue_chunk(const char* zb, int n0, int g,
                                            uint32_t smb, int tid) {
    const int mt = g / NCHUNK, kc = g - mt * NCHUNK;
    const int m0 = mt * TTN;
    const int seg = kc / 9, sub = kc - seg * 9;
    const int aoff2 = (((seg == 1) ? 576 : 0) + sub * 64) * 2;  // bytes
    const int boff2 = (((seg == 2) ? 576 : 0) + sub * 64) * 2;
    const uint32_t sA = smb + (g & 3) * STAGE;
    const uint32_t sB = sA + 16384;
    #pragma unroll
    for (int i = 0; i < 4; ++i) {           // A: 128 rows x 128 B
        const int s = tid + i * 256, row = s >> 3, cb = (s & 7) * 16;
        cp16(sA + row * 128 + (cb ^ ((row & 7) << 4)),
             zb + (size_t)(n0 + row) * ROWB + aoff2 + cb);
    }
    #pragma unroll
    for (int i = 0; i < 8; ++i) {           // B: 256 rows x 128 B
        const int s = tid + i * 256, row = s >> 3, cb = (s & 7) * 16;
        cp16(sB + row * 128 + (cb ^ ((row & 7) << 4)),
             zb + (size_t)(m0 + row) * ROWB + boff2 + cb);
    }
}

__global__ __launch_bounds__(256, 1) void gemm_top3_mma() {
    extern __shared__ char sm[];
    const int tid = threadIdx.x, wid = tid >> 5, lane = tid & 31;
    const int b = blockIdx.y, n0 = blockIdx.x * TTM;
    const char* zb = (const char*)g_za + (size_t)b * NHW * ROWB;
    const uint32_t smb = s2u(sm);

    const int wr = wid >> 1, wc = wid & 1;    // warp tile: rows wr*32, cols wc*128
    const int quad = lane >> 3, qr = lane & 7;
    const uint32_t sw = (uint32_t)qr << 4;    // per-lane swizzle term (row&7 == qr)

    const int arow0 = wr * 32 + (quad & 1) * 8 + qr;     // + a*16
    const int akb   = (quad >> 1) * 16;
    const int brow0 = wc * 128 + (quad >> 1) * 8 + qr;   // + njp*16
    const int bkb   = (quad & 1) * 16;

    float tv[4][3];
    int   ti[4][3];
    #pragma unroll
    for (int r = 0; r < 4; ++r)
        #pragma unroll
        for (int s = 0; s < 3; ++s) { tv[r][s] = -1e30f; ti[r][s] = 0x7fffffff; }

    // Prologue: fill stages 0..2
    #pragma unroll
    for (int p = 0; p < 3; ++p) { issue_chunk(zb, n0, p, smb, tid); CP_COMMIT(); }

    int g = 0;
    for (int mt = 0; mt < NMT; ++mt) {
        float acc[2][16][4];
        #pragma unroll
        for (int a = 0; a < 2; ++a)
            #pragma unroll
            for (int nj = 0; nj < 16; ++nj)
                #pragma unroll
                for (int q = 0; q < 4; ++q) acc[a][nj][q] = 0.f;

        for (int kc = 0; kc < NCHUNK; ++kc, ++g) {
            CP_WAIT2();             // stage g resident
            __syncthreads();        // everyone done computing stage (g-1)%4
            if (g + 3 < NG) issue_chunk(zb, n0, g + 3, smb, tid);
            CP_COMMIT();            // unconditional: keeps group counting uniform

            const uint32_t sA = smb + (g & 3) * STAGE;
            const uint32_t sB = sA + 16384;
            #pragma unroll
            for (int ks = 0; ks < 4; ++ks) {
                uint32_t aF[2][4];
                #pragma unroll
                for (int a = 0; a < 2; ++a) {
                    const uint32_t kb = (uint32_t)(ks * 32 + akb) ^ sw;
                    LDSM4(aF[a][0], aF[a][1], aF[a][2], aF[a][3],
                          sA + (uint32_t)(arow0 + a * 16) * 128 + kb);
                }
                #pragma unroll
                for (int njp = 0; njp < 8; ++njp) {
                    uint32_t b0, b1, b2, b3;
                    const uint32_t kb = (uint32_t)(ks * 32 + bkb) ^ sw;
                    LDSM4(b0, b1, b2, b3,
                          sB + (uint32_t)(brow0 + njp * 16) * 128 + kb);
                    mma16816(acc[0][njp * 2],     aF[0][0], aF[0][1], aF[0][2], aF[0][3], b0, b1);
                    mma16816(acc[0][njp * 2 + 1], aF[0][0], aF[0][1], aF[0][2], aF[0][3], b2, b3);
                    mma16816(acc[1][njp * 2],     aF[1][0], aF[1][1], aF[1][2], aF[1][3], b0, b1);
                    mma16816(acc[1][njp * 2 + 1], aF[1][0], aF[1][1], aF[1][2], aF[1][3], b2, b3);
                }
            }
        }

        // Streaming top-3 update for this m-step (ascending m; '>' keeps lowest idx)
        const int mbase = mt * TTN + wc * 128 + (lane & 3) * 2;
        #pragma unroll
        for (int a = 0; a < 2; ++a) {
            #pragma unroll
            for (int nj = 0; nj < 16; ++nj) {
                const int mcol = mbase + nj * 8;
                top3upd(tv[a * 2],     ti[a * 2],     acc[a][nj][0], mcol);
                top3upd(tv[a * 2],     ti[a * 2],     acc[a][nj][1], mcol + 1);
                top3upd(tv[a * 2 + 1], ti[a * 2 + 1], acc[a][nj][2], mcol);
                top3upd(tv[a * 2 + 1], ti[a * 2 + 1], acc[a][nj][3], mcol + 1);
            }
        }
    }

    // Merge 8 candidate sets per row (2 warp-cols x 4 lane-groups); tie -> lower idx
    __syncthreads();
    float* cv = (float*)sm;                 // [128][8][3]  12 KB
    int*   ci = (int*)(sm + 12288);         // [128][8][3]  12 KB
    const int slot = wc * 4 + (lane & 3);
    #pragma unroll
    for (int a = 0; a < 2; ++a)
        #pragma unroll
        for (int hh = 0; hh < 2; ++hh) {
            const int row = wr * 32 + a * 16 + hh * 8 + (lane >> 2);
            #pragma unroll
            for (int s = 0; s < 3; ++s) {
                cv[row * 24 + slot * 3 + s] = tv[a * 2 + hh][s];
                ci[row * 24 + slot * 3 + s] = ti[a * 2 + hh][s];
            }
        }
    __syncthreads();
    if (tid < TTM) {
        float b0v = -1e30f, b1v = -1e30f, b2v = -1e30f;
        int   j0 = 0x7fffffff, j1 = 0x7fffffff, j2 = 0x7fffffff;
        #pragma unroll
        for (int e = 0; e < 24; ++e) {
            const float v = cv[tid * 24 + e];
            const int   m = ci[tid * 24 + e];
            if (v > b2v || (v == b2v && m < j2)) {
                if (v > b1v || (v == b1v && m < j1)) {
                    if (v > b0v || (v == b0v && m < j0)) {
                        b2v = b1v; j2 = j1;
                        b1v = b0v; j1 = j0;
                        b0v = v;   j0 = m;
                    } else {
                        b2v = b1v; j2 = j1;
                        b1v = v;   j1 = m;
                    }
                } else {
                    b2v = v; j2 = m;
                }
            }
        }
        const int base = (b * NHW + n0 + tid) * 3;
        g_top[base] = j0; g_top[base + 1] = j1; g_top[base + 2] = j2;
    }
}

// ---------------------------------------------------------------------------
// Kernel 4: gather K (reference's scrambled reshape), scores, softmax, output.
// ---------------------------------------------------------------------------
__device__ __forceinline__ float gatherK(const float* __restrict__ xt_b, int b,
                                         int mh, int mw, int r, int c) {
    const int d  = r * 64 + c;
    const int cc = d / 9;
    const int jj = d - cc * 9;
    const int hh = mh + jj / 3 - 1;
    const int ww = mw + jj % 3 - 1;
    float v = 0.f;
    if ((unsigned)hh < 64u && (unsigned)ww < 64u)
        v = __fdiv_rn(xt_b[(hh * 64 + ww) * 64 + cc],
                      g_norm[(b * NC + cc) * 9 + jj]);
    return v;
}

__global__ void attn_kernel(float* __restrict__ out) {
    const int gw = (blockIdx.x * blockDim.x + threadIdx.x) >> 5;
    const int lane = threadIdx.x & 31;
    if (gw >= NB * NHW) return;
    const int b = gw >> 12;
    const int n = gw & (NHW - 1);
    const int h = n >> 6, w = n & 63;
    const int c0 = lane, c1 = lane + 32;

    const float* __restrict__ xt_b = g_xt + (size_t)b * NHW * NC;
    const float q0 = xt_b[(h * 64 + w) * 64 + c0];
    const float q1 = xt_b[(h * 64 + w) * 64 + c1];

    int mi[3];
    mi[0] = g_top[gw * 3];
    mi[1] = g_top[gw * 3 + 1];
    mi[2] = g_top[gw * 3 + 2];

    float kv0[27], kv1[27];
    #pragma unroll
    for (int k = 0; k < 3; ++k) {
        const int mh = mi[k] >> 6, mw = mi[k] & 63;
        #pragma unroll
        for (int r = 0; r < 9; ++r) {
            kv0[k * 9 + r] = gatherK(xt_b, b, mh, mw, r, c0);
            kv1[k * 9 + r] = gatherK(xt_b, b, mh, mw, r, c1);
        }
    }

    float s[27];
    #pragma unroll
    for (int e = 0; e < 27; ++e) {
        float t = q0 * kv0[e] + q1 * kv1[e];
        #pragma unroll
        for (int o = 16; o > 0; o >>= 1) t += __shfl_xor_sync(0xffffffffu, t, o);
        s[e] = t * 0.125f;   // / sqrt(64)
    }

    float mx = s[0];
    #pragma unroll
    for (int e = 1; e < 27; ++e) mx = fmaxf(mx, s[e]);
    float sum = 0.f;
    #pragma unroll
    for (int e = 0; e < 27; ++e) { s[e] = expf(s[e] - mx); sum += s[e]; }

    float o0 = 0.f, o1 = 0.f;
    #pragma unroll
    for (int e = 0; e < 27; ++e) {
        const float we = __fdiv_rn(s[e], sum);
        o0 += we * kv0[e];
        o1 += we * kv1[e];
    }
    out[(size_t)gw * 64 + c0] = o0;
    out[(size_t)gw * 64 + c1] = o1;
}

// ---------------------------------------------------------------------------
extern "C" void kernel_launch(void* const* d_in, const int* in_sizes, int n_in,
                              void* d_out, int out_size) {
    const float* x = (const float*)d_in[0];
    float* out = (float*)d_out;

    norms_kernel<<<NB * NC, 256>>>(x);
    splitz_kernel<<<dim3(NHW / 32, NKD / 32, NB), dim3(32, 8)>>>(x);
    transpose_kernel<<<(NB * NC * NHW + 255) / 256, 256>>>(x);

    cudaFuncSetAttribute(gemm_top3_mma,
                         cudaFuncAttributeMaxDynamicSharedMemorySize, SMEMB);
    gemm_top3_mma<<<dim3(NHW / TTM, NB), 256, SMEMB>>>();

    attn_kernel<<<(NB * NHW * 32 + 255) / 256, 256>>>(out);
}

// round 12
// speedup vs baseline: 2.4996x; 1.1426x over previous
#include <cuda_runtime.h>
#include <cuda_bf16.h>
#include <math.h>
#include <stdint.h>

// Problem constants
constexpr int NB  = 4;
constexpr int NC  = 64;
constexpr int NHW = 4096;     // 64*64
constexpr int NKD = 576;      // C*9

// Split-K bf16 GEMM config
constexpr int KP     = 1152;          // stored K' = [hi(576) | lo(576)]
constexpr int ROWB   = KP * 2;        // 2304 bytes per n-row
constexpr int TTM    = 128;           // rows (n) per CTA
constexpr int TTN    = 256;           // cols (m) per m-step
constexpr int NMT    = NHW / TTN;     // 16 m-steps
constexpr int NCHUNK = 27;            // 27 x 64 = effective K 1728 (hihi+lohi+hilo)
constexpr int NG     = NMT * NCHUNK;  // 432 chunks total

constexpr int STAGE  = 49152;         // A 16KB + B 32KB per stage
constexpr int SMEMB  = 4 * STAGE;     // 192 KB, 4-stage pipeline

// Scratch (static __device__: no allocations allowed)
__device__ __nv_bfloat16 g_za[(size_t)NB * NHW * KP];   // [b][n][hi|lo]  ~37.7MB
__device__ float g_norm[NB * NC * 9];                   // per-(b,c,j) L2 norms
__device__ int   g_top[NB * NHW * 3];                   // top-3 indices per (b,n)

// ---------------------------------------------------------------------------
// PTX helpers (sm_80-era: safe for plain sm_103 ptxas target)
// ---------------------------------------------------------------------------
__device__ __forceinline__ uint32_t s2u(const void* p) {
    uint32_t a;
    asm("{ .reg .u64 t; cvta.to.shared.u64 t, %1; cvt.u32.u64 %0, t; }"
        : "=r"(a) : "l"(p));
    return a;
}
__device__ __forceinline__ void cp16(uint32_t s, const void* g) {
    asm volatile("cp.async.cg.shared.global [%0], [%1], 16;"
                 :: "r"(s), "l"(g) : "memory");
}
#define CP_COMMIT()  asm volatile("cp.async.commit_group;" ::: "memory")
#define CP_WAIT2()   asm volatile("cp.async.wait_group 2;" ::: "memory")

#define LDSM4(r0, r1, r2, r3, a) \
    asm volatile("ldmatrix.sync.aligned.m8n8.x4.shared.b16 {%0,%1,%2,%3}, [%4];" \
                 : "=r"(r0), "=r"(r1), "=r"(r2), "=r"(r3) : "r"(a))

__device__ __forceinline__ void mma16816(float* c, uint32_t a0, uint32_t a1,
                                         uint32_t a2, uint32_t a3,
                                         uint32_t b0, uint32_t b1) {
    asm volatile(
        "mma.sync.aligned.m16n8k16.row.col.f32.bf16.bf16.f32 "
        "{%0,%1,%2,%3}, {%4,%5,%6,%7}, {%8,%9}, {%0,%1,%2,%3};"
        : "+f"(c[0]), "+f"(c[1]), "+f"(c[2]), "+f"(c[3])
        : "r"(a0), "r"(a1), "r"(a2), "r"(a3), "r"(b0), "r"(b1));
}

__device__ __forceinline__ void top3upd(float tv[3], int ti[3], float v, int m) {
    if (v > tv[2]) {
        if (v > tv[1]) {
            if (v > tv[0]) {
                tv[2] = tv[1]; ti[2] = ti[1];
                tv[1] = tv[0]; ti[1] = ti[0];
                tv[0] = v;     ti[0] = m;
            } else {
                tv[2] = tv[1]; ti[2] = ti[1];
                tv[1] = v;     ti[1] = m;
            }
        } else {
            tv[2] = v; ti[2] = m;
        }
    }
}

// ---------------------------------------------------------------------------
// Kernel 1: shifted norms via border decomposition.
// ---------------------------------------------------------------------------
__global__ void norms_kernel(const float* __restrict__ x) {
    const int bc = blockIdx.x;
    const float* xp = x + (size_t)bc * NHW;

    float s = 0.f, r0 = 0.f, r63 = 0.f, cl = 0.f, cr = 0.f;
    for (int idx = threadIdx.x; idx < NHW; idx += blockDim.x) {
        float v = xp[idx]; v *= v;
        const int h = idx >> 6, w = idx & 63;
        s += v;
        if (h == 0)  r0  += v;
        if (h == 63) r63 += v;
        if (w == 0)  cl  += v;
        if (w == 63) cr  += v;
    }
    __shared__ float red[5][256];
    red[0][threadIdx.x] = s;  red[1][threadIdx.x] = r0; red[2][threadIdx.x] = r63;
    red[3][threadIdx.x] = cl; red[4][threadIdx.x] = cr;
    __syncthreads();
    for (int o = 128; o > 0; o >>= 1) {
        if (threadIdx.x < o)
            for (int q = 0; q < 5; ++q) red[q][threadIdx.x] += red[q][threadIdx.x + o];
        __syncthreads();
    }
    if (threadIdx.x == 0) {
        const float S = red[0][0], R0 = red[1][0], R63 = red[2][0];
        const float CL = red[3][0], CR = red[4][0];
        float x00 = xp[0],        x0e = xp[63];
        float xe0 = xp[63 * 64],  xee = xp[63 * 64 + 63];
        x00 *= x00; x0e *= x0e; xe0 *= xe0; xee *= xee;
        #pragma unroll
        for (int kh = 0; kh < 3; ++kh)
            #pragma unroll
            for (int kw = 0; kw < 3; ++kw) {
                float n2 = S;
                if (kh == 0) n2 -= R63;
                if (kh == 2) n2 -= R0;
                if (kw == 0) n2 -= CR;
                if (kw == 2) n2 -= CL;
                if (kh == 0 && kw == 0) n2 += xee;
                if (kh == 0 && kw == 2) n2 += xe0;
                if (kh == 2 && kw == 0) n2 += x0e;
                if (kh == 2 && kw == 2) n2 += x00;
                float nrm = sqrtf(fmaxf(n2, 0.f));
                nrm = fmaxf(nrm, 1e-12f);
                g_norm[bc * 9 + kh * 3 + kw] = nrm;
            }
    }
}

// ---------------------------------------------------------------------------
// Kernel 2: build split-bf16 normalized unfold, transposed to [b][n][hi|lo].
// ---------------------------------------------------------------------------
__global__ void splitz_kernel(const float* __restrict__ x) {
    __shared__ float tl[32][33];
    const int b = blockIdx.z, d0 = blockIdx.y * 32, n0 = blockIdx.x * 32;
    const int tx = threadIdx.x, ty = threadIdx.y;   // 32x8
    #pragma unroll
    for (int i = 0; i < 4; ++i) {
        const int d = d0 + ty + i * 8, n = n0 + tx;
        const int c = d / 9, jj = d - c * 9;
        const int h = (n >> 6) + jj / 3 - 1, w = (n & 63) + jj % 3 - 1;
        float v = 0.f;
        if ((unsigned)h < 64u && (unsigned)w < 64u)
            v = __fdiv_rn(x[(((size_t)b * NC + c) * 64 + h) * 64 + w],
                          g_norm[(b * NC + c) * 9 + jj]);
        tl[ty + i * 8][tx] = v;
    }
    __syncthreads();
    #pragma unroll
    for (int i = 0; i < 4; ++i) {
        const int n = n0 + ty + i * 8, d = d0 + tx;
        const float z = tl[tx][ty + i * 8];
        const __nv_bfloat16 h = __float2bfloat16(z);
        const __nv_bfloat16 l = __float2bfloat16(z - __bfloat162float(h));
        __nv_bfloat16* row = g_za + ((size_t)b * NHW + n) * KP;
        row[d] = h;
        row[576 + d] = l;
    }
}

// ---------------------------------------------------------------------------
// Kernel 3: HMMA bf16 split GEMM (R = Z^T Z) with fused streaming top-3.
// 512 threads, 16 warps as 4(rows)x4(cols), warp tile 32x64, mma.m16n8k16,
// 4-stage cp.async pipeline, one __syncthreads per chunk.
// ---------------------------------------------------------------------------
__device__ __forceinline__ void issue_chunk(const char* zb, int n0, int g,
                                            uint32_t smb, int tid) {
    const int mt = g / NCHUNK, kc = g - mt * NCHUNK;
    const int m0 = mt * TTN;
    const int seg = kc / 9, sub = kc - seg * 9;
    const int aoff2 = (((seg == 1) ? 576 : 0) + sub * 64) * 2;  // bytes
    const int boff2 = (((seg == 2) ? 576 : 0) + sub * 64) * 2;
    const uint32_t sA = smb + (g & 3) * STAGE;
    const uint32_t sB = sA + 16384;
    #pragma unroll
    for (int i = 0; i < 2; ++i) {           // A: 128 rows x 128 B
        const int s = tid + i * 512, row = s >> 3, cb = (s & 7) * 16;
        cp16(sA + row * 128 + (cb ^ ((row & 7) << 4)),
             zb + (size_t)(n0 + row) * ROWB + aoff2 + cb);
    }
    #pragma unroll
    for (int i = 0; i < 4; ++i) {           // B: 256 rows x 128 B
        const int s = tid + i * 512, row = s >> 3, cb = (s & 7) * 16;
        cp16(sB + row * 128 + (cb ^ ((row & 7) << 4)),
             zb + (size_t)(m0 + row) * ROWB + boff2 + cb);
    }
}

__global__ __launch_bounds__(512, 1) void gemm_top3_mma() {
    extern __shared__ char sm[];
    const int tid = threadIdx.x, wid = tid >> 5, lane = tid & 31;
    const int b = blockIdx.y, n0 = blockIdx.x * TTM;
    const char* zb = (const char*)g_za + (size_t)b * NHW * ROWB;
    const uint32_t smb = s2u(sm);

    const int wr = wid >> 2, wc = wid & 3;    // warp tile: rows wr*32, cols wc*64
    const int quad = lane >> 3, qr = lane & 7;
    const uint32_t sw = (uint32_t)qr << 4;    // per-lane swizzle term (row&7 == qr)

    const int arow0 = wr * 32 + (quad & 1) * 8 + qr;     // + a*16
    const int akb   = (quad >> 1) * 16;
    const int brow0 = wc * 64 + (quad >> 1) * 8 + qr;    // + njp*16
    const int bkb   = (quad & 1) * 16;

    float tv[4][3];
    int   ti[4][3];
    #pragma unroll
    for (int r = 0; r < 4; ++r)
        #pragma unroll
        for (int s = 0; s < 3; ++s) { tv[r][s] = -1e30f; ti[r][s] = 0x7fffffff; }

    // Prologue: fill stages 0..2
    #pragma unroll
    for (int p = 0; p < 3; ++p) { issue_chunk(zb, n0, p, smb, tid); CP_COMMIT(); }

    int g = 0;
    for (int mt = 0; mt < NMT; ++mt) {
        float acc[2][8][4];
        #pragma unroll
        for (int a = 0; a < 2; ++a)
            #pragma unroll
            for (int nj = 0; nj < 8; ++nj)
                #pragma unroll
                for (int q = 0; q < 4; ++q) acc[a][nj][q] = 0.f;

        for (int kc = 0; kc < NCHUNK; ++kc, ++g) {
            CP_WAIT2();             // stage g resident
            __syncthreads();        // everyone done computing stage (g-1)%4
            if (g + 3 < NG) issue_chunk(zb, n0, g + 3, smb, tid);
            CP_COMMIT();            // unconditional: keeps group counting uniform

            const uint32_t sA = smb + (g & 3) * STAGE;
            const uint32_t sB = sA + 16384;
            #pragma unroll
            for (int ks = 0; ks < 4; ++ks) {
                uint32_t aF[2][4];
                #pragma unroll
                for (int a = 0; a < 2; ++a) {
                    const uint32_t kb = (uint32_t)(ks * 32 + akb) ^ sw;
                    LDSM4(aF[a][0], aF[a][1], aF[a][2], aF[a][3],
                          sA + (uint32_t)(arow0 + a * 16) * 128 + kb);
                }
                #pragma unroll
                for (int njp = 0; njp < 4; ++njp) {
                    uint32_t b0, b1, b2, b3;
                    const uint32_t kb = (uint32_t)(ks * 32 + bkb) ^ sw;
                    LDSM4(b0, b1, b2, b3,
                          sB + (uint32_t)(brow0 + njp * 16) * 128 + kb);
                    mma16816(acc[0][njp * 2],     aF[0][0], aF[0][1], aF[0][2], aF[0][3], b0, b1);
                    mma16816(acc[0][njp * 2 + 1], aF[0][0], aF[0][1], aF[0][2], aF[0][3], b2, b3);
                    mma16816(acc[1][njp * 2],     aF[1][0], aF[1][1], aF[1][2], aF[1][3], b0, b1);
                    mma16816(acc[1][njp * 2 + 1], aF[1][0], aF[1][1], aF[1][2], aF[1][3], b2, b3);
                }
            }
        }

        // Streaming top-3 update for this m-step (ascending m; '>' keeps lowest idx)
        const int mbase = mt * TTN + wc * 64 + (lane & 3) * 2;
        #pragma unroll
        for (int a = 0; a < 2; ++a) {
            #pragma unroll
            for (int nj = 0; nj < 8; ++nj) {
                const int mcol = mbase + nj * 8;
                top3upd(tv[a * 2],     ti[a * 2],     acc[a][nj][0], mcol);
                top3upd(tv[a * 2],     ti[a * 2],     acc[a][nj][1], mcol + 1);
                top3upd(tv[a * 2 + 1], ti[a * 2 + 1], acc[a][nj][2], mcol);
                top3upd(tv[a * 2 + 1], ti[a * 2 + 1], acc[a][nj][3], mcol + 1);
            }
        }
    }

    // Merge 16 candidate sets per row (4 warp-cols x 4 lane-groups); tie -> lower idx
    __syncthreads();
    float* cv = (float*)sm;                 // [128][16][3]  24 KB
    int*   ci = (int*)(sm + 24576);         // [128][16][3]  24 KB
    const int slot = wc * 4 + (lane & 3);
    #pragma unroll
    for (int a = 0; a < 2; ++a)
        #pragma unroll
        for (int hh = 0; hh < 2; ++hh) {
            const int row = wr * 32 + a * 16 + hh * 8 + (lane >> 2);
            #pragma unroll
            for (int s = 0; s < 3; ++s) {
                cv[row * 48 + slot * 3 + s] = tv[a * 2 + hh][s];
                ci[row * 48 + slot * 3 + s] = ti[a * 2 + hh][s];
            }
        }
    __syncthreads();
    if (tid < TTM) {
        float b0v = -1e30f, b1v = -1e30f, b2v = -1e30f;
        int   j0 = 0x7fffffff, j1 = 0x7fffffff, j2 = 0x7fffffff;
        #pragma unroll
        for (int e = 0; e < 48; ++e) {
            const float v = cv[tid * 48 + e];
            const int   m = ci[tid * 48 + e];
            if (v > b2v || (v == b2v && m < j2)) {
                if (v > b1v || (v == b1v && m < j1)) {
                    if (v > b0v || (v == b0v && m < j0)) {
                        b2v = b1v; j2 = j1;
                        b1v = b0v; j1 = j0;
                        b0v = v;   j0 = m;
                    } else {
                        b2v = b1v; j2 = j1;
                        b1v = v;   j1 = m;
                    }
                } else {
                    b2v = v; j2 = m;
                }
            }
        }
        const int base = (b * NHW + n0 + tid) * 3;
        g_top[base] = j0; g_top[base + 1] = j1; g_top[base + 2] = j2;
    }
}

// ---------------------------------------------------------------------------
// Kernel 4: attention epilogue. K values come straight from g_za (hi+lo
// reconstructs z to ~2^-16 relative), with d = r*64 + c contiguous ->
// fully coalesced warp reads. Q read directly from x.
// ---------------------------------------------------------------------------
__global__ void attn_kernel(const float* __restrict__ x, float* __restrict__ out) {
    const int gw = (blockIdx.x * blockDim.x + threadIdx.x) >> 5;
    const int lane = threadIdx.x & 31;
    if (gw >= NB * NHW) return;
    const int b = gw >> 12;
    const int n = gw & (NHW - 1);
    const int c0 = lane, c1 = lane + 32;

    // Q[b,n,c] = x[b][c][n]
    const float q0 = x[((size_t)b * NC + c0) * NHW + n];
    const float q1 = x[((size_t)b * NC + c1) * NHW + n];

    int mi[3];
    mi[0] = g_top[gw * 3];
    mi[1] = g_top[gw * 3 + 1];
    mi[2] = g_top[gw * 3 + 2];

    float kv0[27], kv1[27];
    #pragma unroll
    for (int k = 0; k < 3; ++k) {
        const __nv_bfloat16* __restrict__ row =
            g_za + ((size_t)b * NHW + mi[k]) * KP;
        #pragma unroll
        for (int r = 0; r < 9; ++r) {
            const int d0 = r * 64 + c0;
            const int d1 = r * 64 + c1;
            kv0[k * 9 + r] = __bfloat162float(row[d0]) + __bfloat162float(row[576 + d0]);
            kv1[k * 9 + r] = __bfloat162float(row[d1]) + __bfloat162float(row[576 + d1]);
        }
    }

    float s[27];
    #pragma unroll
    for (int e = 0; e < 27; ++e) {
        float t = q0 * kv0[e] + q1 * kv1[e];
        #pragma unroll
        for (int o = 16; o > 0; o >>= 1) t += __shfl_xor_sync(0xffffffffu, t, o);
        s[e] = t * 0.125f;   // / sqrt(64)
    }

    float mx = s[0];
    #pragma unroll
    for (int e = 1; e < 27; ++e) mx = fmaxf(mx, s[e]);
    float sum = 0.f;
    #pragma unroll
    for (int e = 0; e < 27; ++e) { s[e] = expf(s[e] - mx); sum += s[e]; }

    float o0 = 0.f, o1 = 0.f;
    #pragma unroll
    for (int e = 0; e < 27; ++e) {
        const float we = __fdiv_rn(s[e], sum);
        o0 += we * kv0[e];
        o1 += we * kv1[e];
    }
    out[(size_t)gw * 64 + c0] = o0;
    out[(size_t)gw * 64 + c1] = o1;
}

// ---------------------------------------------------------------------------
extern "C" void kernel_launch(void* const* d_in, const int* in_sizes, int n_in,
                              void* d_out, int out_size) {
    const float* x = (const float*)d_in[0];
    float* out = (float*)d_out;

    norms_kernel<<<NB * NC, 256>>>(x);
    splitz_kernel<<<dim3(NHW / 32, NKD / 32, NB), dim3(32, 8)>>>(x);

    cudaFuncSetAttribute(gemm_top3_mma,
                         cudaFuncAttributeMaxDynamicSharedMemorySize, SMEMB);
    gemm_top3_mma<<<dim3(NHW / TTM, NB), 512, SMEMB>>>();

    attn_kernel<<<(NB * NHW * 32 + 255) / 256, 256>>>(x, out);
}

// round 13
// speedup vs baseline: 4.8134x; 1.9257x over previous
#include <cuda_runtime.h>
#include <cuda_bf16.h>
#include <math.h>
#include <stdint.h>

// Problem constants
constexpr int NB  = 4;
constexpr int NC  = 64;
constexpr int NHW = 4096;     // 64*64
constexpr int NKD = 576;      // C*9
constexpr int NBLK = 32;      // 4096 / 128 row-blocks
constexpr int NPAIR = NBLK * (NBLK + 1) / 2;   // 528 upper-tri tiles

// Split-K bf16 GEMM config
constexpr int KP     = 1152;          // stored K' = [hi(576) | lo(576)]
constexpr int ROWB   = KP * 2;        // 2304 bytes per n-row
constexpr int NCHUNK = 27;            // 27 x 64 = effective K 1728 (hihi+lohi+hilo)

constexpr int STAGE  = 32768;         // A 16KB + B 16KB per stage
constexpr int SMEMB  = 3 * STAGE;     // 96 KB, 3-stage pipeline
constexpr int ESTRIDE = 130;          // epilogue smem row stride (floats)

// Scratch (static __device__: no allocations allowed)
__device__ __nv_bfloat16 g_za[(size_t)NB * NHW * KP];   // [b][n][hi|lo]  ~37.7MB
__device__ float g_norm[NB * NC * 9];                   // per-(b,c,j) L2 norms
__device__ float g_cv[(size_t)NB * NHW * NBLK * 3];     // candidate values 6.3MB
__device__ int   g_ci[(size_t)NB * NHW * NBLK * 3];     // candidate indices 6.3MB
__device__ int   g_top[NB * NHW * 3];                   // final top-3 per (b,n)

// ---------------------------------------------------------------------------
// PTX helpers (sm_80-era: safe for plain sm_103 ptxas target)
// ---------------------------------------------------------------------------
__device__ __forceinline__ uint32_t s2u(const void* p) {
    uint32_t a;
    asm("{ .reg .u64 t; cvta.to.shared.u64 t, %1; cvt.u32.u64 %0, t; }"
        : "=r"(a) : "l"(p));
    return a;
}
__device__ __forceinline__ void cp16(uint32_t s, const void* g) {
    asm volatile("cp.async.cg.shared.global [%0], [%1], 16;"
                 :: "r"(s), "l"(g) : "memory");
}
#define CP_COMMIT()  asm volatile("cp.async.commit_group;" ::: "memory")
#define CP_WAIT1()   asm volatile("cp.async.wait_group 1;" ::: "memory")

#define LDSM4(r0, r1, r2, r3, a) \
    asm volatile("ldmatrix.sync.aligned.m8n8.x4.shared.b16 {%0,%1,%2,%3}, [%4];" \
                 : "=r"(r0), "=r"(r1), "=r"(r2), "=r"(r3) : "r"(a))

__device__ __forceinline__ void mma16816(float* c, uint32_t a0, uint32_t a1,
                                         uint32_t a2, uint32_t a3,
                                         uint32_t b0, uint32_t b1) {
    asm volatile(
        "mma.sync.aligned.m16n8k16.row.col.f32.bf16.bf16.f32 "
        "{%0,%1,%2,%3}, {%4,%5,%6,%7}, {%8,%9}, {%0,%1,%2,%3};"
        : "+f"(c[0]), "+f"(c[1]), "+f"(c[2]), "+f"(c[3])
        : "r"(a0), "r"(a1), "r"(a2), "r"(a3), "r"(b0), "r"(b1));
}

// ---------------------------------------------------------------------------
// Kernel 1: shifted norms via border decomposition.
// ---------------------------------------------------------------------------
__global__ void norms_kernel(const float* __restrict__ x) {
    const int bc = blockIdx.x;
    const float* xp = x + (size_t)bc * NHW;

    float s = 0.f, r0 = 0.f, r63 = 0.f, cl = 0.f, cr = 0.f;
    for (int idx = threadIdx.x; idx < NHW; idx += blockDim.x) {
        float v = xp[idx]; v *= v;
        const int h = idx >> 6, w = idx & 63;
        s += v;
        if (h == 0)  r0  += v;
        if (h == 63) r63 += v;
        if (w == 0)  cl  += v;
        if (w == 63) cr  += v;
    }
    __shared__ float red[5][256];
    red[0][threadIdx.x] = s;  red[1][threadIdx.x] = r0; red[2][threadIdx.x] = r63;
    red[3][threadIdx.x] = cl; red[4][threadIdx.x] = cr;
    __syncthreads();
    for (int o = 128; o > 0; o >>= 1) {
        if (threadIdx.x < o)
            for (int q = 0; q < 5; ++q) red[q][threadIdx.x] += red[q][threadIdx.x + o];
        __syncthreads();
    }
    if (threadIdx.x == 0) {
        const float S = red[0][0], R0 = red[1][0], R63 = red[2][0];
        const float CL = red[3][0], CR = red[4][0];
        float x00 = xp[0],        x0e = xp[63];
        float xe0 = xp[63 * 64],  xee = xp[63 * 64 + 63];
        x00 *= x00; x0e *= x0e; xe0 *= xe0; xee *= xee;
        #pragma unroll
        for (int kh = 0; kh < 3; ++kh)
            #pragma unroll
            for (int kw = 0; kw < 3; ++kw) {
                float n2 = S;
                if (kh == 0) n2 -= R63;
                if (kh == 2) n2 -= R0;
                if (kw == 0) n2 -= CR;
                if (kw == 2) n2 -= CL;
                if (kh == 0 && kw == 0) n2 += xee;
                if (kh == 0 && kw == 2) n2 += xe0;
                if (kh == 2 && kw == 0) n2 += x0e;
                if (kh == 2 && kw == 2) n2 += x00;
                float nrm = sqrtf(fmaxf(n2, 0.f));
                nrm = fmaxf(nrm, 1e-12f);
                g_norm[bc * 9 + kh * 3 + kw] = nrm;
            }
    }
}

// ---------------------------------------------------------------------------
// Kernel 2: build split-bf16 normalized unfold, transposed to [b][n][hi|lo].
// ---------------------------------------------------------------------------
__global__ void splitz_kernel(const float* __restrict__ x) {
    __shared__ float tl[32][33];
    const int b = blockIdx.z, d0 = blockIdx.y * 32, n0 = blockIdx.x * 32;
    const int tx = threadIdx.x, ty = threadIdx.y;   // 32x8
    #pragma unroll
    for (int i = 0; i < 4; ++i) {
        const int d = d0 + ty + i * 8, n = n0 + tx;
        const int c = d / 9, jj = d - c * 9;
        const int h = (n >> 6) + jj / 3 - 1, w = (n & 63) + jj % 3 - 1;
        float v = 0.f;
        if ((unsigned)h < 64u && (unsigned)w < 64u)
            v = __fdiv_rn(x[(((size_t)b * NC + c) * 64 + h) * 64 + w],
                          g_norm[(b * NC + c) * 9 + jj]);
        tl[ty + i * 8][tx] = v;
    }
    __syncthreads();
    #pragma unroll
    for (int i = 0; i < 4; ++i) {
        const int n = n0 + ty + i * 8, d = d0 + tx;
        const float z = tl[tx][ty + i * 8];
        const __nv_bfloat16 h = __float2bfloat16(z);
        const __nv_bfloat16 l = __float2bfloat16(z - __bfloat162float(h));
        __nv_bfloat16* row = g_za + ((size_t)b * NHW + n) * KP;
        row[d] = h;
        row[576 + d] = l;
    }
}

// ---------------------------------------------------------------------------
// Kernel 3: HMMA bf16 split GEMM on upper-triangular 128x128 tiles of the
// symmetric R. Each tile emits top-3 candidates for its rows (row scan) AND
// its columns (col scan = rows of the transposed tile). 256 threads, 8 warps
// as 4x2, warp tile 32x64, 3-stage cp.async pipeline.
// ---------------------------------------------------------------------------
__device__ __forceinline__ void issue_chunk(const char* zb, int n0, int m0,
                                            int kc, int stg, uint32_t smb, int tid) {
    const int seg = kc / 9, sub = kc - seg * 9;
    const int aoff2 = (((seg == 1) ? 576 : 0) + sub * 64) * 2;  // bytes
    const int boff2 = (((seg == 2) ? 576 : 0) + sub * 64) * 2;
    const uint32_t sA = smb + stg * STAGE;
    const uint32_t sB = sA + 16384;
    #pragma unroll
    for (int i = 0; i < 4; ++i) {           // A: 128 rows x 128 B
        const int s = tid + i * 256, row = s >> 3, cb = (s & 7) * 16;
        cp16(sA + row * 128 + (cb ^ ((row & 7) << 4)),
             zb + (size_t)(n0 + row) * ROWB + aoff2 + cb);
    }
    #pragma unroll
    for (int i = 0; i < 4; ++i) {           // B: 128 rows x 128 B
        const int s = tid + i * 256, row = s >> 3, cb = (s & 7) * 16;
        cp16(sB + row * 128 + (cb ^ ((row & 7) << 4)),
             zb + (size_t)(m0 + row) * ROWB + boff2 + cb);
    }
}

__global__ __launch_bounds__(256, 2) void gemm_top3_sym() {
    extern __shared__ char sm[];
    const int tid = threadIdx.x, wid = tid >> 5, lane = tid & 31;
    const int b = blockIdx.y;
    // pair p -> (I, J), I <= J
    int I = 0, base = 0;
    {
        const int p = blockIdx.x;
        while (base + (NBLK - I) <= p) { base += NBLK - I; ++I; }
        // J = I + (p - base)
        base = I + (blockIdx.x - base);
    }
    const int J = base;
    const int n0 = I * 128, m0 = J * 128;

    const char* zb = (const char*)g_za + (size_t)b * NHW * ROWB;
    const uint32_t smb = s2u(sm);

    const int wr = wid >> 1, wc = wid & 1;    // warp tile: rows wr*32, cols wc*64
    const int quad = lane >> 3, qr = lane & 7;
    const uint32_t sw = (uint32_t)qr << 4;

    const int arow0 = wr * 32 + (quad & 1) * 8 + qr;     // + a*16
    const int akb   = (quad >> 1) * 16;
    const int brow0 = wc * 64 + (quad >> 1) * 8 + qr;    // + njp*16
    const int bkb   = (quad & 1) * 16;

    float acc[2][8][4];
    #pragma unroll
    for (int a = 0; a < 2; ++a)
        #pragma unroll
        for (int nj = 0; nj < 8; ++nj)
            #pragma unroll
            for (int q = 0; q < 4; ++q) acc[a][nj][q] = 0.f;

    // Prologue: stages 0,1
    issue_chunk(zb, n0, m0, 0, 0, smb, tid); CP_COMMIT();
    issue_chunk(zb, n0, m0, 1, 1, smb, tid); CP_COMMIT();

    for (int kc = 0; kc < NCHUNK; ++kc) {
        CP_WAIT1();             // chunk kc resident
        __syncthreads();        // all warps done reading stage (kc+2)%3
        if (kc + 2 < NCHUNK) issue_chunk(zb, n0, m0, kc + 2, (kc + 2) % 3, smb, tid);
        CP_COMMIT();

        const uint32_t sA = smb + (kc % 3) * STAGE;
        const uint32_t sB = sA + 16384;
        #pragma unroll
        for (int ks = 0; ks < 4; ++ks) {
            uint32_t aF[2][4];
            #pragma unroll
            for (int a = 0; a < 2; ++a) {
                const uint32_t kb = (uint32_t)(ks * 32 + akb) ^ sw;
                LDSM4(aF[a][0], aF[a][1], aF[a][2], aF[a][3],
                      sA + (uint32_t)(arow0 + a * 16) * 128 + kb);
            }
            #pragma unroll
            for (int njp = 0; njp < 4; ++njp) {
                uint32_t b0, b1, b2, b3;
                const uint32_t kb = (uint32_t)(ks * 32 + bkb) ^ sw;
                LDSM4(b0, b1, b2, b3,
                      sB + (uint32_t)(brow0 + njp * 16) * 128 + kb);
                mma16816(acc[0][njp * 2],     aF[0][0], aF[0][1], aF[0][2], aF[0][3], b0, b1);
                mma16816(acc[0][njp * 2 + 1], aF[0][0], aF[0][1], aF[0][2], aF[0][3], b2, b3);
                mma16816(acc[1][njp * 2],     aF[1][0], aF[1][1], aF[1][2], aF[1][3], b0, b1);
                mma16816(acc[1][njp * 2 + 1], aF[1][0], aF[1][1], aF[1][2], aF[1][3], b2, b3);
            }
        }
    }

    // Epilogue: dump tile to smem [128][ESTRIDE], then row & col scans.
    __syncthreads();   // stage smem reuse safe
    float* t = (float*)sm;
    {
        const int r1 = wr * 32 + (lane >> 2);
        const int cp = wc * 64 + (lane & 3) * 2;
        #pragma unroll
        for (int a = 0; a < 2; ++a)
            #pragma unroll
            for (int nj = 0; nj < 8; ++nj) {
                const int rr = r1 + a * 16;
                const int cc = cp + nj * 8;
                *(float2*)&t[rr * ESTRIDE + cc]       = *(float2*)&acc[a][nj][0];
                *(float2*)&t[(rr + 8) * ESTRIDE + cc] = *(float2*)&acc[a][nj][2];
            }
    }
    __syncthreads();

    // threads 0..127: row scan (row tid), slot J; threads 128..255: col scan
    // (col tid-128), slot I (skip on diagonal).
    {
        const bool isrow = tid < 128;
        if (isrow || I != J) {
            const int e = isrow ? tid : tid - 128;
            float b0v = -1e30f, b1v = -1e30f, b2v = -1e30f;
            int   j0 = 0, j1 = 0, j2 = 0;
            #pragma unroll 4
            for (int u = 0; u < 128; ++u) {
                const float v = isrow ? t[e * ESTRIDE + u] : t[u * ESTRIDE + e];
                if (v > b2v) {
                    if (v > b1v) {
                        if (v > b0v) {
                            b2v = b1v; j2 = j1;
                            b1v = b0v; j1 = j0;
                            b0v = v;   j0 = u;
                        } else {
                            b2v = b1v; j2 = j1;
                            b1v = v;   j1 = u;
                        }
                    } else {
                        b2v = v; j2 = u;
                    }
                }
            }
            const int row  = isrow ? (n0 + e) : (m0 + e);
            const int moff = isrow ? m0 : n0;
            const int slot = isrow ? J : I;
            const size_t o = (((size_t)b * NHW + row) * NBLK + slot) * 3;
            g_cv[o] = b0v;     g_cv[o + 1] = b1v;     g_cv[o + 2] = b2v;
            g_ci[o] = moff + j0; g_ci[o + 1] = moff + j1; g_ci[o + 2] = moff + j2;
        }
    }
}

// ---------------------------------------------------------------------------
// Kernel 3b: merge 32 candidate slots per row -> final top-3.
// ---------------------------------------------------------------------------
__global__ void merge_kernel() {
    const int gidx = blockIdx.x * blockDim.x + threadIdx.x;
    if (gidx >= NB * NHW) return;
    const float* cv = g_cv + (size_t)gidx * NBLK * 3;
    const int*   ci = g_ci + (size_t)gidx * NBLK * 3;
    float b0v = -1e30f, b1v = -1e30f, b2v = -1e30f;
    int   j0 = 0x7fffffff, j1 = 0x7fffffff, j2 = 0x7fffffff;
    for (int e = 0; e < NBLK * 3; ++e) {
        const float v = cv[e];
        const int   m = ci[e];
        if (v > b2v || (v == b2v && m < j2)) {
            if (v > b1v || (v == b1v && m < j1)) {
                if (v > b0v || (v == b0v && m < j0)) {
                    b2v = b1v; j2 = j1;
                    b1v = b0v; j1 = j0;
                    b0v = v;   j0 = m;
                } else {
                    b2v = b1v; j2 = j1;
                    b1v = v;   j1 = m;
                }
            } else {
                b2v = v; j2 = m;
            }
        }
    }
    g_top[gidx * 3] = j0; g_top[gidx * 3 + 1] = j1; g_top[gidx * 3 + 2] = j2;
}

// ---------------------------------------------------------------------------
// Kernel 4: attention epilogue. K from g_za (hi+lo), coalesced; Q from x.
// ---------------------------------------------------------------------------
__global__ void attn_kernel(const float* __restrict__ x, float* __restrict__ out) {
    const int gw = (blockIdx.x * blockDim.x + threadIdx.x) >> 5;
    const int lane = threadIdx.x & 31;
    if (gw >= NB * NHW) return;
    const int b = gw >> 12;
    const int n = gw & (NHW - 1);
    const int c0 = lane, c1 = lane + 32;

    const float q0 = x[((size_t)b * NC + c0) * NHW + n];
    const float q1 = x[((size_t)b * NC + c1) * NHW + n];

    int mi[3];
    mi[0] = g_top[gw * 3];
    mi[1] = g_top[gw * 3 + 1];
    mi[2] = g_top[gw * 3 + 2];

    float kv0[27], kv1[27];
    #pragma unroll
    for (int k = 0; k < 3; ++k) {
        const __nv_bfloat16* __restrict__ row =
            g_za + ((size_t)b * NHW + mi[k]) * KP;
        #pragma unroll
        for (int r = 0; r < 9; ++r) {
            const int d0 = r * 64 + c0;
            const int d1 = r * 64 + c1;
            kv0[k * 9 + r] = __bfloat162float(row[d0]) + __bfloat162float(row[576 + d0]);
            kv1[k * 9 + r] = __bfloat162float(row[d1]) + __bfloat162float(row[576 + d1]);
        }
    }

    float s[27];
    #pragma unroll
    for (int e = 0; e < 27; ++e) {
        float tt = q0 * kv0[e] + q1 * kv1[e];
        #pragma unroll
        for (int o = 16; o > 0; o >>= 1) tt += __shfl_xor_sync(0xffffffffu, tt, o);
        s[e] = tt * 0.125f;   // / sqrt(64)
    }

    float mx = s[0];
    #pragma unroll
    for (int e = 1; e < 27; ++e) mx = fmaxf(mx, s[e]);
    float sum = 0.f;
    #pragma unroll
    for (int e = 0; e < 27; ++e) { s[e] = expf(s[e] - mx); sum += s[e]; }

    float o0 = 0.f, o1 = 0.f;
    #pragma unroll
    for (int e = 0; e < 27; ++e) {
        const float we = __fdiv_rn(s[e], sum);
        o0 += we * kv0[e];
        o1 += we * kv1[e];
    }
    out[(size_t)gw * 64 + c0] = o0;
    out[(size_t)gw * 64 + c1] = o1;
}

// ---------------------------------------------------------------------------
extern "C" void kernel_launch(void* const* d_in, const int* in_sizes, int n_in,
                              void* d_out, int out_size) {
    const float* x = (const float*)d_in[0];
    float* out = (float*)d_out;

    norms_kernel<<<NB * NC, 256>>>(x);
    splitz_kernel<<<dim3(NHW / 32, NKD / 32, NB), dim3(32, 8)>>>(x);

    cudaFuncSetAttribute(gemm_top3_sym,
                         cudaFuncAttributeMaxDynamicSharedMemorySize, SMEMB);
    gemm_top3_sym<<<dim3(NPAIR, NB), 256, SMEMB>>>();

    merge_kernel<<<(NB * NHW + 255) / 256, 256>>>();
    attn_kernel<<<(NB * NHW * 32 + 255) / 256, 256>>>(x, out);
}